// round 13
// baseline (speedup 1.0000x reference)
#include <cuda_runtime.h>
#include <cuda_fp16.h>
#include <math.h>

#define BB   4
#define TT   8
#define NN   2000
#define FIN  158
#define DD   128
#define HH   4
#define CC   32
#define MAXDEG 256
#define SDEG 128
#define ROWS (BB*NN)
#define FRONT_COMPUTE 500            // 16 rows each
#define ADJ_BLOCKS (ROWS/4)          // 4 rows each

// ---------------- device scratch ----------------
__device__ float  g_h  [ROWS*DD];
__device__ float  g_h2 [ROWS*DD];
__device__ __half g_xh [ROWS*DD];    // fp16 aggregation operand
__device__ float4 g_es4[ROWS];
__device__ float4 g_ed4[ROWS];
__device__ int    g_adj[ROWS*MAXDEG];
__device__ int    g_deg[ROWS];
__device__ float  g_hf [ROWS*CC];

__device__ __forceinline__ void store_half8(__half* dst, float4 v) {
    __half2 p0 = __floats2half2_rn(v.x, v.y);
    __half2 p1 = __floats2half2_rn(v.z, v.w);
    uint2 u;
    u.x = *(unsigned*)&p0; u.y = *(unsigned*)&p1;
    *(uint2*)dst = u;
}

// ---- packed f32x2 helpers (fma.rn.f32x2: same rounding as 2x fmaf) ----
__device__ __forceinline__ unsigned long long bcast2(float x) {
    unsigned long long r;
    asm("mov.b64 %0, {%1, %1};" : "=l"(r) : "f"(x));
    return r;
}
__device__ __forceinline__ void ffma2(unsigned long long &d,
                                      unsigned long long a, unsigned long long b) {
    asm("fma.rn.f32x2 %0, %1, %2, %0;" : "+l"(d) : "l"(a), "l"(b));
}
__device__ __forceinline__ float2 unpack2(unsigned long long v) {
    float2 f;
    asm("mov.b64 {%0, %1}, %2;" : "=f"(f.x), "=f"(f.y) : "l"(v));
    return f;
}
// 2 rows x 4 output dims per k-iter: 2 packs + 4 packed FMAs
#define FMA2P(w2, x0, x1, A0xy, A0zw, A1xy, A1zw) { \
    unsigned long long _b0 = bcast2(x0), _b1 = bcast2(x1); \
    ffma2(A0xy, _b0, (w2).x); ffma2(A0zw, _b0, (w2).y); \
    ffma2(A1xy, _b1, (w2).x); ffma2(A1zw, _b1, (w2).y); }

// ============ kernel 1 (fused): (inproj+LN+ReLU -> proj0+att0) || adjacency build ============
__global__ void k_front(const float* __restrict__ x_alpha,
                        const float* __restrict__ W_in,
                        const float* __restrict__ b_in,
                        const float* __restrict__ ln_g,
                        const float* __restrict__ ln_b,
                        const float* __restrict__ sg,
                        const float* __restrict__ W0,
                        const float* __restrict__ as0,
                        const float* __restrict__ ad0)
{
    int tid = threadIdx.x;
    if (blockIdx.x >= FRONT_COMPUTE) {
        // ---- adjacency: 4 rows, 64 threads each ----
        int base = (blockIdx.x - FRONT_COMPUTE) * 4;
        int sub = tid >> 6, c = tid & 63;
        int row = base + sub;
        int i = row % NN;
        __shared__ int cnt[4];
        if (tid < 4) cnt[tid] = 0;
        __syncthreads();
        const float4* rp = (const float4*)(sg + (size_t)row*NN);
        #pragma unroll 2
        for (int t = c; t < NN/4; t += 64) {
            float4 v = rp[t];
            int j0 = 4*t;
            if (v.x > 0.f || j0   == i) { int k = atomicAdd(&cnt[sub],1); if (k < MAXDEG) g_adj[row*MAXDEG+k] = j0;   }
            if (v.y > 0.f || j0+1 == i) { int k = atomicAdd(&cnt[sub],1); if (k < MAXDEG) g_adj[row*MAXDEG+k] = j0+1; }
            if (v.z > 0.f || j0+2 == i) { int k = atomicAdd(&cnt[sub],1); if (k < MAXDEG) g_adj[row*MAXDEG+k] = j0+2; }
            if (v.w > 0.f || j0+3 == i) { int k = atomicAdd(&cnt[sub],1); if (k < MAXDEG) g_adj[row*MAXDEG+k] = j0+3; }
        }
        __syncthreads();
        if (c == 0) g_deg[row] = cnt[sub] < MAXDEG ? cnt[sub] : MAXDEG;
        return;
    }

    // ---- compute blocks: 16 rows ----
    __shared__ float xr[16][FIN];
    __shared__ __align__(16) float sh[16][DD];
    int row0 = blockIdx.x * 16;
    {
        int b = row0 / NN;                    // 16 | NN: blocks never straddle a batch
        const float* xp = x_alpha + (((size_t)b*TT + (TT-1))*NN + (row0 - b*NN))*FIN;
        for (int idx = tid; idx < 16*FIN; idx += 256)
            xr[idx/FIN][idx%FIN] = xp[idx];
    }
    __syncthreads();

    int w = tid >> 5, lane = tid & 31;
    int r0 = 2*w, r1 = 2*w + 1;

    // phase A: h = relu(LN(x@W_in + b_in)) ; 4-deep prefetch + packed f32x2 FMA
    float4 a0, a1;
    {
        ulonglong2 bi2 = *(const ulonglong2*)(b_in + 4*lane);
        unsigned long long A0xy = bi2.x, A0zw = bi2.y, A1xy = bi2.x, A1zw = bi2.y;
        const ulonglong2* wp = (const ulonglong2*)W_in + lane;   // row k at wp[k*32]
        ulonglong2 p0 = wp[0], p1 = wp[32], p2 = wp[64], p3 = wp[96];
        for (int k = 0; k < 152; k += 4) {
            ulonglong2 n0 = wp[(k+4)*32], n1 = wp[(k+5)*32],
                       n2 = wp[(k+6)*32], n3 = wp[(k+7)*32];
            FMA2P(p0, xr[r0][k  ], xr[r1][k  ], A0xy, A0zw, A1xy, A1zw);
            FMA2P(p1, xr[r0][k+1], xr[r1][k+1], A0xy, A0zw, A1xy, A1zw);
            FMA2P(p2, xr[r0][k+2], xr[r1][k+2], A0xy, A0zw, A1xy, A1zw);
            FMA2P(p3, xr[r0][k+3], xr[r1][k+3], A0xy, A0zw, A1xy, A1zw);
            p0 = n0; p1 = n1; p2 = n2; p3 = n3;
        }
        FMA2P(p0, xr[r0][152], xr[r1][152], A0xy, A0zw, A1xy, A1zw);
        FMA2P(p1, xr[r0][153], xr[r1][153], A0xy, A0zw, A1xy, A1zw);
        FMA2P(p2, xr[r0][154], xr[r1][154], A0xy, A0zw, A1xy, A1zw);
        FMA2P(p3, xr[r0][155], xr[r1][155], A0xy, A0zw, A1xy, A1zw);
        ulonglong2 q0 = wp[156*32], q1 = wp[157*32];
        FMA2P(q0, xr[r0][156], xr[r1][156], A0xy, A0zw, A1xy, A1zw);
        FMA2P(q1, xr[r0][157], xr[r1][157], A0xy, A0zw, A1xy, A1zw);
        float2 t;
        t = unpack2(A0xy); a0.x = t.x; a0.y = t.y;
        t = unpack2(A0zw); a0.z = t.x; a0.w = t.y;
        t = unpack2(A1xy); a1.x = t.x; a1.y = t.y;
        t = unpack2(A1zw); a1.z = t.x; a1.w = t.y;
    }
    float4 gg = *(const float4*)(ln_g + 4*lane);
    float4 gb = *(const float4*)(ln_b + 4*lane);
    {
        float s = a0.x + a0.y + a0.z + a0.w;
        for (int o = 16; o; o >>= 1) s += __shfl_xor_sync(0xffffffffu, s, o);
        float mean = s * (1.0f/DD);
        float dx=a0.x-mean, dy=a0.y-mean, dz=a0.z-mean, dw=a0.w-mean;
        float q = dx*dx + dy*dy + dz*dz + dw*dw;
        for (int o = 16; o; o >>= 1) q += __shfl_xor_sync(0xffffffffu, q, o);
        float sc = rsqrtf(q * (1.0f/DD) + 1e-5f);
        float4 y;
        y.x = fmaxf(dx*sc*gg.x + gb.x, 0.f); y.y = fmaxf(dy*sc*gg.y + gb.y, 0.f);
        y.z = fmaxf(dz*sc*gg.z + gb.z, 0.f); y.w = fmaxf(dw*sc*gg.w + gb.w, 0.f);
        *(float4*)(g_h + (size_t)(row0+r0)*DD + 4*lane) = y;
        *(float4*)(&sh[r0][4*lane]) = y;
    }
    {
        float s = a1.x + a1.y + a1.z + a1.w;
        for (int o = 16; o; o >>= 1) s += __shfl_xor_sync(0xffffffffu, s, o);
        float mean = s * (1.0f/DD);
        float dx=a1.x-mean, dy=a1.y-mean, dz=a1.z-mean, dw=a1.w-mean;
        float q = dx*dx + dy*dy + dz*dz + dw*dw;
        for (int o = 16; o; o >>= 1) q += __shfl_xor_sync(0xffffffffu, q, o);
        float sc = rsqrtf(q * (1.0f/DD) + 1e-5f);
        float4 y;
        y.x = fmaxf(dx*sc*gg.x + gb.x, 0.f); y.y = fmaxf(dy*sc*gg.y + gb.y, 0.f);
        y.z = fmaxf(dz*sc*gg.z + gb.z, 0.f); y.w = fmaxf(dw*sc*gg.w + gb.w, 0.f);
        *(float4*)(g_h + (size_t)(row0+r1)*DD + 4*lane) = y;
        *(float4*)(&sh[r1][4*lane]) = y;
    }
    __syncthreads();

    // phase B: xh0 = h@W0 (fp16 out) ; 4-deep prefetch + packed f32x2 FMA
    float4 c0, c1;
    {
        unsigned long long A0xy = 0, A0zw = 0, A1xy = 0, A1zw = 0;
        const ulonglong2* wp = (const ulonglong2*)W0 + lane;
        ulonglong2 p0 = wp[0], p1 = wp[32], p2 = wp[64], p3 = wp[96];
        for (int k = 0; k < DD-4; k += 4) {
            ulonglong2 n0 = wp[(k+4)*32], n1 = wp[(k+5)*32],
                       n2 = wp[(k+6)*32], n3 = wp[(k+7)*32];
            FMA2P(p0, sh[r0][k  ], sh[r1][k  ], A0xy, A0zw, A1xy, A1zw);
            FMA2P(p1, sh[r0][k+1], sh[r1][k+1], A0xy, A0zw, A1xy, A1zw);
            FMA2P(p2, sh[r0][k+2], sh[r1][k+2], A0xy, A0zw, A1xy, A1zw);
            FMA2P(p3, sh[r0][k+3], sh[r1][k+3], A0xy, A0zw, A1xy, A1zw);
            p0 = n0; p1 = n1; p2 = n2; p3 = n3;
        }
        FMA2P(p0, sh[r0][124], sh[r1][124], A0xy, A0zw, A1xy, A1zw);
        FMA2P(p1, sh[r0][125], sh[r1][125], A0xy, A0zw, A1xy, A1zw);
        FMA2P(p2, sh[r0][126], sh[r1][126], A0xy, A0zw, A1xy, A1zw);
        FMA2P(p3, sh[r0][127], sh[r1][127], A0xy, A0zw, A1xy, A1zw);
        float2 t;
        t = unpack2(A0xy); c0.x = t.x; c0.y = t.y;
        t = unpack2(A0zw); c0.z = t.x; c0.w = t.y;
        t = unpack2(A1xy); c1.x = t.x; c1.y = t.y;
        t = unpack2(A1zw); c1.z = t.x; c1.w = t.y;
    }
    store_half8(g_xh + (size_t)(row0+r0)*DD + 4*lane, c0);
    store_half8(g_xh + (size_t)(row0+r1)*DD + 4*lane, c1);

    float4 av = *(const float4*)(as0 + 4*lane);
    float4 dv = *(const float4*)(ad0 + 4*lane);
    float es0 = c0.x*av.x + c0.y*av.y + c0.z*av.z + c0.w*av.w;
    float ed0 = c0.x*dv.x + c0.y*dv.y + c0.z*dv.z + c0.w*dv.w;
    float es1 = c1.x*av.x + c1.y*av.y + c1.z*av.z + c1.w*av.w;
    float ed1 = c1.x*dv.x + c1.y*dv.y + c1.z*dv.z + c1.w*dv.w;
    for (int o = 4; o; o >>= 1) {
        es0 += __shfl_xor_sync(0xffffffffu, es0, o);
        ed0 += __shfl_xor_sync(0xffffffffu, ed0, o);
        es1 += __shfl_xor_sync(0xffffffffu, es1, o);
        ed1 += __shfl_xor_sync(0xffffffffu, ed1, o);
    }
    if ((lane & 7) == 0) {
        int h = lane >> 3;
        ((float*)(g_es4 + row0 + r0))[h] = es0;
        ((float*)(g_ed4 + row0 + r0))[h] = ed0;
        ((float*)(g_es4 + row0 + r1))[h] = es1;
        ((float*)(g_ed4 + row0 + r1))[h] = ed1;
    }
}

// ============ k_proj (layer 1): 16 rows/block, 4-deep prefetch + packed f32x2 FMA ============
__global__ void k_proj(const float* __restrict__ hin,
                       const float* __restrict__ W,
                       const float* __restrict__ as_,
                       const float* __restrict__ ad_)
{
    __shared__ __align__(16) float hr[16][DD];
    int row0 = blockIdx.x * 16, tid = threadIdx.x;
    {
        const float4* src = (const float4*)(hin + (size_t)row0*DD);
        float4* dst = (float4*)&hr[0][0];
        dst[tid] = src[tid];
        dst[tid + 256] = src[tid + 256];
    }
    __syncthreads();

    int w = tid >> 5, lane = tid & 31;
    int r0 = 2*w, r1 = 2*w + 1;
    float4 a0, a1;
    {
        unsigned long long A0xy = 0, A0zw = 0, A1xy = 0, A1zw = 0;
        const ulonglong2* wp = (const ulonglong2*)W + lane;
        ulonglong2 p0 = wp[0], p1 = wp[32], p2 = wp[64], p3 = wp[96];
        for (int k = 0; k < DD-4; k += 4) {
            ulonglong2 n0 = wp[(k+4)*32], n1 = wp[(k+5)*32],
                       n2 = wp[(k+6)*32], n3 = wp[(k+7)*32];
            FMA2P(p0, hr[r0][k  ], hr[r1][k  ], A0xy, A0zw, A1xy, A1zw);
            FMA2P(p1, hr[r0][k+1], hr[r1][k+1], A0xy, A0zw, A1xy, A1zw);
            FMA2P(p2, hr[r0][k+2], hr[r1][k+2], A0xy, A0zw, A1xy, A1zw);
            FMA2P(p3, hr[r0][k+3], hr[r1][k+3], A0xy, A0zw, A1xy, A1zw);
            p0 = n0; p1 = n1; p2 = n2; p3 = n3;
        }
        FMA2P(p0, hr[r0][124], hr[r1][124], A0xy, A0zw, A1xy, A1zw);
        FMA2P(p1, hr[r0][125], hr[r1][125], A0xy, A0zw, A1xy, A1zw);
        FMA2P(p2, hr[r0][126], hr[r1][126], A0xy, A0zw, A1xy, A1zw);
        FMA2P(p3, hr[r0][127], hr[r1][127], A0xy, A0zw, A1xy, A1zw);
        float2 t;
        t = unpack2(A0xy); a0.x = t.x; a0.y = t.y;
        t = unpack2(A0zw); a0.z = t.x; a0.w = t.y;
        t = unpack2(A1xy); a1.x = t.x; a1.y = t.y;
        t = unpack2(A1zw); a1.z = t.x; a1.w = t.y;
    }
    store_half8(g_xh + (size_t)(row0+r0)*DD + 4*lane, a0);
    store_half8(g_xh + (size_t)(row0+r1)*DD + 4*lane, a1);

    float4 av = *(const float4*)(as_ + 4*lane);
    float4 dv = *(const float4*)(ad_ + 4*lane);
    float es0 = a0.x*av.x + a0.y*av.y + a0.z*av.z + a0.w*av.w;
    float ed0 = a0.x*dv.x + a0.y*dv.y + a0.z*dv.z + a0.w*dv.w;
    float es1 = a1.x*av.x + a1.y*av.y + a1.z*av.z + a1.w*av.w;
    float ed1 = a1.x*dv.x + a1.y*dv.y + a1.z*dv.z + a1.w*dv.w;
    for (int o = 4; o; o >>= 1) {
        es0 += __shfl_xor_sync(0xffffffffu, es0, o);
        ed0 += __shfl_xor_sync(0xffffffffu, ed0, o);
        es1 += __shfl_xor_sync(0xffffffffu, es1, o);
        ed1 += __shfl_xor_sync(0xffffffffu, ed1, o);
    }
    if ((lane & 7) == 0) {
        int h = lane >> 3;
        ((float*)(g_es4 + row0 + r0))[h] = es0;
        ((float*)(g_ed4 + row0 + r0))[h] = ed0;
        ((float*)(g_es4 + row0 + r1))[h] = es1;
        ((float*)(g_ed4 + row0 + r1))[h] = ed1;
    }
}

// ============ k_gat: 4 rows/block, 2 warps/row (parity split), fp16 gather, __expf ============
// MODE 0: hout = hin + elu(agg + bias[128])
// MODE 1: g_hf = head-mean(agg) + bias[32]
template <int MODE>
__global__ void __launch_bounds__(256, 8) k_gat(
                      const float* __restrict__ hin,
                      const float* __restrict__ bias,
                      float* __restrict__ hout)
{
    int tid = threadIdx.x, w = tid >> 5, lane = tid & 31;
    int rsel = w >> 1, p = w & 1;
    int row0 = blockIdx.x * 4;
    int row = row0 + rsel;
    int bN = (row / NN) * NN;

    __shared__ int   soff_s[4][SDEG];
    __shared__ __align__(16) float salp_s[4][SDEG*4];
    __shared__ float ssum_s[4][2][HH];
    __shared__ float sinv_s[4][HH];
    __shared__ __align__(16) float spart_s[4][2][DD];

    int deg = g_deg[row];
    if (deg > SDEG) deg = SDEG;
    float4 edv = g_ed4[row];

    // phase 1: scores -> __expf, parity-split over k; per-head partial sums
    float4 sums = {0.f, 0.f, 0.f, 0.f};
    for (int k = p + 2*lane; k < deg; k += 64) {
        int j = g_adj[row*MAXDEG + k];
        soff_s[rsel][k] = (bN + j) * DD;
        float4 es = g_es4[bN + j];
        float4 s;
        s.x = edv.x + es.x; s.x = s.x >= 0.f ? s.x : 0.2f*s.x; s.x = __expf(s.x);
        s.y = edv.y + es.y; s.y = s.y >= 0.f ? s.y : 0.2f*s.y; s.y = __expf(s.y);
        s.z = edv.z + es.z; s.z = s.z >= 0.f ? s.z : 0.2f*s.z; s.z = __expf(s.z);
        s.w = edv.w + es.w; s.w = s.w >= 0.f ? s.w : 0.2f*s.w; s.w = __expf(s.w);
        sums.x += s.x; sums.y += s.y; sums.z += s.z; sums.w += s.w;
        *(float4*)(&salp_s[rsel][k*4]) = s;
    }
    for (int o = 16; o; o >>= 1) {
        sums.x += __shfl_xor_sync(0xffffffffu, sums.x, o);
        sums.y += __shfl_xor_sync(0xffffffffu, sums.y, o);
        sums.z += __shfl_xor_sync(0xffffffffu, sums.z, o);
        sums.w += __shfl_xor_sync(0xffffffffu, sums.w, o);
    }
    if (lane == 0) {
        ssum_s[rsel][p][0] = sums.x; ssum_s[rsel][p][1] = sums.y;
        ssum_s[rsel][p][2] = sums.z; ssum_s[rsel][p][3] = sums.w;
    }
    __syncthreads();
    if (p == 0 && lane < HH)
        sinv_s[rsel][lane] = 1.0f / (ssum_s[rsel][0][lane] + ssum_s[rsel][1][lane]);

    // phase 2: gather, parity-split, fp16 rows, MLP 4 per warp (8 per row)
    {
        const __half* base = g_xh + 4*lane;
        const int*   so = soff_s[rsel];
        const float* al = &salp_s[rsel][lane >> 3];
        float4 A0 = {0,0,0,0}, A1 = A0;
        int k = p;
        for (; k + 6 < deg; k += 8) {
            float a0 = al[4*k];       uint2 u0 = *(const uint2*)(base + so[k]);
            float a1 = al[4*(k+2)];   uint2 u1 = *(const uint2*)(base + so[k+2]);
            float a2 = al[4*(k+4)];   uint2 u2 = *(const uint2*)(base + so[k+4]);
            float a3 = al[4*(k+6)];   uint2 u3 = *(const uint2*)(base + so[k+6]);
            float2 f;
            f = __half22float2(*(__half2*)&u0.x); A0.x=fmaf(a0,f.x,A0.x); A0.y=fmaf(a0,f.y,A0.y);
            f = __half22float2(*(__half2*)&u0.y); A0.z=fmaf(a0,f.x,A0.z); A0.w=fmaf(a0,f.y,A0.w);
            f = __half22float2(*(__half2*)&u1.x); A1.x=fmaf(a1,f.x,A1.x); A1.y=fmaf(a1,f.y,A1.y);
            f = __half22float2(*(__half2*)&u1.y); A1.z=fmaf(a1,f.x,A1.z); A1.w=fmaf(a1,f.y,A1.w);
            f = __half22float2(*(__half2*)&u2.x); A0.x=fmaf(a2,f.x,A0.x); A0.y=fmaf(a2,f.y,A0.y);
            f = __half22float2(*(__half2*)&u2.y); A0.z=fmaf(a2,f.x,A0.z); A0.w=fmaf(a2,f.y,A0.w);
            f = __half22float2(*(__half2*)&u3.x); A1.x=fmaf(a3,f.x,A1.x); A1.y=fmaf(a3,f.y,A1.y);
            f = __half22float2(*(__half2*)&u3.y); A1.z=fmaf(a3,f.x,A1.z); A1.w=fmaf(a3,f.y,A1.w);
        }
        for (; k < deg; k += 2) {
            float a0 = al[4*k];       uint2 u0 = *(const uint2*)(base + so[k]);
            float2 f;
            f = __half22float2(*(__half2*)&u0.x); A0.x=fmaf(a0,f.x,A0.x); A0.y=fmaf(a0,f.y,A0.y);
            f = __half22float2(*(__half2*)&u0.y); A0.z=fmaf(a0,f.x,A0.z); A0.w=fmaf(a0,f.y,A0.w);
        }
        A0.x += A1.x; A0.y += A1.y; A0.z += A1.z; A0.w += A1.w;
        *(float4*)(&spart_s[rsel][p][4*lane]) = A0;
    }
    __syncthreads();

    // phase 3: combine parities, scale by softmax inverse, epilogue
    #pragma unroll
    for (int half = 0; half < 2; ++half) {
        int idx = tid + 256*half;            // 512 = 4 rows x 128 dims
        int r = idx >> 7, d = idx & 127;
        float v = (spart_s[r][0][d] + spart_s[r][1][d]) * sinv_s[r][d >> 5];
        if (MODE == 0) {
            float t = v + bias[d];
            float e = t > 0.f ? t : (__expf(t) - 1.f);      // ELU(alpha=1)
            hout[(size_t)(row0+r)*DD + d] = hin[(size_t)(row0+r)*DD + d] + e;
        } else {
            spart_s[r][0][d] = v;                           // staging for head-mean
        }
    }
    if (MODE == 1) {
        __syncthreads();
        if (tid < 4*CC) {
            int r = tid >> 5, c = tid & 31;
            g_hf[(size_t)(row0+r)*CC + c] =
                0.25f * (spart_s[r][0][c] + spart_s[r][0][32+c]
                       + spart_s[r][0][64+c] + spart_s[r][0][96+c]) + bias[c];
        }
    }
}

// ============ k_out: out = g_hf @ W_out + b_out ; 16 rows/block, Wout in smem ============
__global__ void k_out(const float* __restrict__ Wout,
                      const float* __restrict__ bout,
                      float* __restrict__ out)
{
    __shared__ __align__(16) float4 sW[CC*DD/4];   // 16 KB, loaded once per block
    __shared__ float shf[16*CC];                   // 2 KB
    int row0 = blockIdx.x * 16, tid = threadIdx.x;

    const float4* wsrc = (const float4*)Wout;
    #pragma unroll
    for (int i = 0; i < 4; ++i) sW[tid + 256*i] = wsrc[tid + 256*i];
    const float* hsrc = g_hf + (size_t)row0*CC;
    shf[tid] = hsrc[tid];
    shf[tid + 256] = hsrc[tid + 256];
    __syncthreads();

    #pragma unroll
    for (int it = 0; it < 2; ++it) {
        int idx = tid + 256*it;        // 512 items: (row r, float4-col q)
        int r = idx >> 5, q = idx & 31;
        float4 acc = *(const float4*)(bout + 4*q);
        const float* hr = shf + r*CC;
        #pragma unroll
        for (int c = 0; c < CC; ++c) {
            float x = hr[c];
            float4 wv = sW[c*32 + q];
            acc.x = fmaf(x, wv.x, acc.x); acc.y = fmaf(x, wv.y, acc.y);
            acc.z = fmaf(x, wv.z, acc.z); acc.w = fmaf(x, wv.w, acc.w);
        }
        *(float4*)(out + (size_t)(row0+r)*DD + 4*q) = acc;
    }
}

// ---------------- launch ----------------
extern "C" void kernel_launch(void* const* d_in, const int* in_sizes, int n_in,
                              void* d_out, int out_size)
{
    const float* x_alpha = (const float*)d_in[0];
    const float* sg      = (const float*)d_in[1];
    const float* W_in    = (const float*)d_in[2];
    const float* b_in    = (const float*)d_in[3];
    const float* ln_g    = (const float*)d_in[4];
    const float* ln_b    = (const float*)d_in[5];
    const float* W0      = (const float*)d_in[6];
    const float* as0     = (const float*)d_in[7];
    const float* ad0     = (const float*)d_in[8];
    const float* bias0   = (const float*)d_in[9];
    const float* W1      = (const float*)d_in[10];
    const float* as1     = (const float*)d_in[11];
    const float* ad1     = (const float*)d_in[12];
    const float* bias1   = (const float*)d_in[13];
    const float* W_out   = (const float*)d_in[14];
    const float* b_out   = (const float*)d_in[15];
    float* out = (float*)d_out;

    float *h, *h2;
    cudaGetSymbolAddress((void**)&h,  g_h);
    cudaGetSymbolAddress((void**)&h2, g_h2);

    k_front<<<FRONT_COMPUTE + ADJ_BLOCKS, 256>>>(x_alpha, W_in, b_in, ln_g, ln_b,
                                                 sg, W0, as0, ad0);
    k_gat<0><<<ROWS/4, 256>>>(h, bias0, h2);
    k_proj<<<ROWS/16, 256>>>(h2, W1, as1, ad1);
    k_gat<1><<<ROWS/4, 256>>>(nullptr, bias1, nullptr);
    k_out<<<ROWS/16, 256>>>(W_out, b_out, out);
}

// round 14
// speedup vs baseline: 1.0969x; 1.0969x over previous
#include <cuda_runtime.h>
#include <cuda_fp16.h>
#include <math.h>

#define BB   4
#define TT   8
#define NN   2000
#define FIN  158
#define DD   128
#define HH   4
#define CC   32
#define MAXDEG 256
#define SDEG 128
#define ROWS (BB*NN)
#define FRONT_COMPUTE 500            // 16 rows each
#define ADJ_BLOCKS (ROWS/4)          // 4 rows each

// ---------------- device scratch ----------------
__device__ float  g_h  [ROWS*DD];
__device__ float  g_h2 [ROWS*DD];
__device__ __half g_xh [ROWS*DD];    // fp16 aggregation operand
__device__ float4 g_es4[ROWS];
__device__ float4 g_ed4[ROWS];
__device__ int    g_adj[ROWS*MAXDEG];
__device__ int    g_deg[ROWS];
__device__ float  g_hf [ROWS*CC];

__device__ __forceinline__ void store_half8(__half* dst, float4 v) {
    __half2 p0 = __floats2half2_rn(v.x, v.y);
    __half2 p1 = __floats2half2_rn(v.z, v.w);
    uint2 u;
    u.x = *(unsigned*)&p0; u.y = *(unsigned*)&p1;
    *(uint2*)dst = u;
}

#define FMA2(av, x0, x1, A0, A1) \
    A0.x=fmaf(x0,av.x,A0.x); A0.y=fmaf(x0,av.y,A0.y); A0.z=fmaf(x0,av.z,A0.z); A0.w=fmaf(x0,av.w,A0.w); \
    A1.x=fmaf(x1,av.x,A1.x); A1.y=fmaf(x1,av.y,A1.y); A1.z=fmaf(x1,av.z,A1.z); A1.w=fmaf(x1,av.w,A1.w);

#define ADJ_CHECK(v, j0) \
    if ((v).x > 0.f || (j0)   == i) { int k = atomicAdd(&cnt[sub],1); if (k < MAXDEG) g_adj[row*MAXDEG+k] = (j0);   } \
    if ((v).y > 0.f || (j0)+1 == i) { int k = atomicAdd(&cnt[sub],1); if (k < MAXDEG) g_adj[row*MAXDEG+k] = (j0)+1; } \
    if ((v).z > 0.f || (j0)+2 == i) { int k = atomicAdd(&cnt[sub],1); if (k < MAXDEG) g_adj[row*MAXDEG+k] = (j0)+2; } \
    if ((v).w > 0.f || (j0)+3 == i) { int k = atomicAdd(&cnt[sub],1); if (k < MAXDEG) g_adj[row*MAXDEG+k] = (j0)+3; }

// ============ kernel 1 (fused): (inproj+LN+ReLU -> proj0+att0) || adjacency build ============
__global__ void k_front(const float* __restrict__ x_alpha,
                        const float* __restrict__ W_in,
                        const float* __restrict__ b_in,
                        const float* __restrict__ ln_g,
                        const float* __restrict__ ln_b,
                        const float* __restrict__ sg,
                        const float* __restrict__ W0,
                        const float* __restrict__ as0,
                        const float* __restrict__ ad0)
{
    int tid = threadIdx.x;
    if (blockIdx.x >= FRONT_COMPUTE) {
        // ---- adjacency: 4 rows, 64 threads each; 4 loads in flight ----
        int base = (blockIdx.x - FRONT_COMPUTE) * 4;
        int sub = tid >> 6, c = tid & 63;
        int row = base + sub;
        int i = row % NN;
        __shared__ int cnt[4];
        if (tid < 4) cnt[tid] = 0;
        __syncthreads();
        const float4* rp = (const float4*)(sg + (size_t)row*NN);
        // NN/4 = 500 items per row, 64 threads: groups at c+{0,64,128,192,256,320,384} + guarded c+448
        {
            float4 v0 = rp[c], v1 = rp[c+64], v2 = rp[c+128], v3 = rp[c+192];
            ADJ_CHECK(v0, 4*c);
            ADJ_CHECK(v1, 4*(c+64));
            ADJ_CHECK(v2, 4*(c+128));
            ADJ_CHECK(v3, 4*(c+192));
        }
        {
            float4 v0 = rp[c+256], v1 = rp[c+320], v2 = rp[c+384];
            bool tail = (c < 52);                 // 448+c < 500
            float4 v3 = tail ? rp[c+448] : make_float4(0.f,0.f,0.f,0.f);
            ADJ_CHECK(v0, 4*(c+256));
            ADJ_CHECK(v1, 4*(c+320));
            ADJ_CHECK(v2, 4*(c+384));
            if (tail) { ADJ_CHECK(v3, 4*(c+448)); }
        }
        __syncthreads();
        if (c == 0) g_deg[row] = cnt[sub] < MAXDEG ? cnt[sub] : MAXDEG;
        return;
    }

    // ---- compute blocks: 16 rows ----
    __shared__ float xr[16][FIN];
    __shared__ __align__(16) float sh[16][DD];
    int row0 = blockIdx.x * 16;
    {
        int b = row0 / NN;                    // 16 | NN: blocks never straddle a batch
        const float* xp = x_alpha + (((size_t)b*TT + (TT-1))*NN + (row0 - b*NN))*FIN;
        for (int idx = tid; idx < 16*FIN; idx += 256)
            xr[idx/FIN][idx%FIN] = xp[idx];
    }
    __syncthreads();

    int w = tid >> 5, lane = tid & 31;
    int r0 = 2*w, r1 = 2*w + 1;

    // phase A: h = relu(LN(x@W_in + b_in)) ; 4-deep W prefetch (MLP 4)
    float4 bi = *(const float4*)(b_in + 4*lane);
    float4 a0 = bi, a1 = bi;
    {
        const float4* wp = (const float4*)W_in + lane;     // row k at wp[k*32]
        float4 p0 = wp[0], p1 = wp[32], p2 = wp[64], p3 = wp[96];
        for (int k = 0; k < 152; k += 4) {
            float4 n0 = wp[(k+4)*32], n1 = wp[(k+5)*32],
                   n2 = wp[(k+6)*32], n3 = wp[(k+7)*32];
            FMA2(p0, xr[r0][k  ], xr[r1][k  ], a0, a1);
            FMA2(p1, xr[r0][k+1], xr[r1][k+1], a0, a1);
            FMA2(p2, xr[r0][k+2], xr[r1][k+2], a0, a1);
            FMA2(p3, xr[r0][k+3], xr[r1][k+3], a0, a1);
            p0 = n0; p1 = n1; p2 = n2; p3 = n3;
        }
        FMA2(p0, xr[r0][152], xr[r1][152], a0, a1);
        FMA2(p1, xr[r0][153], xr[r1][153], a0, a1);
        FMA2(p2, xr[r0][154], xr[r1][154], a0, a1);
        FMA2(p3, xr[r0][155], xr[r1][155], a0, a1);
        float4 q0 = wp[156*32], q1 = wp[157*32];
        FMA2(q0, xr[r0][156], xr[r1][156], a0, a1);
        FMA2(q1, xr[r0][157], xr[r1][157], a0, a1);
    }
    float4 gg = *(const float4*)(ln_g + 4*lane);
    float4 gb = *(const float4*)(ln_b + 4*lane);
    {
        float s = a0.x + a0.y + a0.z + a0.w;
        for (int o = 16; o; o >>= 1) s += __shfl_xor_sync(0xffffffffu, s, o);
        float mean = s * (1.0f/DD);
        float dx=a0.x-mean, dy=a0.y-mean, dz=a0.z-mean, dw=a0.w-mean;
        float q = dx*dx + dy*dy + dz*dz + dw*dw;
        for (int o = 16; o; o >>= 1) q += __shfl_xor_sync(0xffffffffu, q, o);
        float sc = rsqrtf(q * (1.0f/DD) + 1e-5f);
        float4 y;
        y.x = fmaxf(dx*sc*gg.x + gb.x, 0.f); y.y = fmaxf(dy*sc*gg.y + gb.y, 0.f);
        y.z = fmaxf(dz*sc*gg.z + gb.z, 0.f); y.w = fmaxf(dw*sc*gg.w + gb.w, 0.f);
        *(float4*)(g_h + (size_t)(row0+r0)*DD + 4*lane) = y;
        *(float4*)(&sh[r0][4*lane]) = y;
    }
    {
        float s = a1.x + a1.y + a1.z + a1.w;
        for (int o = 16; o; o >>= 1) s += __shfl_xor_sync(0xffffffffu, s, o);
        float mean = s * (1.0f/DD);
        float dx=a1.x-mean, dy=a1.y-mean, dz=a1.z-mean, dw=a1.w-mean;
        float q = dx*dx + dy*dy + dz*dz + dw*dw;
        for (int o = 16; o; o >>= 1) q += __shfl_xor_sync(0xffffffffu, q, o);
        float sc = rsqrtf(q * (1.0f/DD) + 1e-5f);
        float4 y;
        y.x = fmaxf(dx*sc*gg.x + gb.x, 0.f); y.y = fmaxf(dy*sc*gg.y + gb.y, 0.f);
        y.z = fmaxf(dz*sc*gg.z + gb.z, 0.f); y.w = fmaxf(dw*sc*gg.w + gb.w, 0.f);
        *(float4*)(g_h + (size_t)(row0+r1)*DD + 4*lane) = y;
        *(float4*)(&sh[r1][4*lane]) = y;
    }
    __syncthreads();

    // phase B: xh0 = h@W0 (fp16 out) ; 4-deep W prefetch
    float4 c0 = {0,0,0,0}, c1 = {0,0,0,0};
    {
        const float4* wp = (const float4*)W0 + lane;
        float4 p0 = wp[0], p1 = wp[32], p2 = wp[64], p3 = wp[96];
        for (int k = 0; k < DD-4; k += 4) {
            float4 n0 = wp[(k+4)*32], n1 = wp[(k+5)*32],
                   n2 = wp[(k+6)*32], n3 = wp[(k+7)*32];
            FMA2(p0, sh[r0][k  ], sh[r1][k  ], c0, c1);
            FMA2(p1, sh[r0][k+1], sh[r1][k+1], c0, c1);
            FMA2(p2, sh[r0][k+2], sh[r1][k+2], c0, c1);
            FMA2(p3, sh[r0][k+3], sh[r1][k+3], c0, c1);
            p0 = n0; p1 = n1; p2 = n2; p3 = n3;
        }
        FMA2(p0, sh[r0][124], sh[r1][124], c0, c1);
        FMA2(p1, sh[r0][125], sh[r1][125], c0, c1);
        FMA2(p2, sh[r0][126], sh[r1][126], c0, c1);
        FMA2(p3, sh[r0][127], sh[r1][127], c0, c1);
    }
    store_half8(g_xh + (size_t)(row0+r0)*DD + 4*lane, c0);
    store_half8(g_xh + (size_t)(row0+r1)*DD + 4*lane, c1);

    float4 av = *(const float4*)(as0 + 4*lane);
    float4 dv = *(const float4*)(ad0 + 4*lane);
    float es0 = c0.x*av.x + c0.y*av.y + c0.z*av.z + c0.w*av.w;
    float ed0 = c0.x*dv.x + c0.y*dv.y + c0.z*dv.z + c0.w*dv.w;
    float es1 = c1.x*av.x + c1.y*av.y + c1.z*av.z + c1.w*av.w;
    float ed1 = c1.x*dv.x + c1.y*dv.y + c1.z*dv.z + c1.w*dv.w;
    for (int o = 4; o; o >>= 1) {
        es0 += __shfl_xor_sync(0xffffffffu, es0, o);
        ed0 += __shfl_xor_sync(0xffffffffu, ed0, o);
        es1 += __shfl_xor_sync(0xffffffffu, es1, o);
        ed1 += __shfl_xor_sync(0xffffffffu, ed1, o);
    }
    if ((lane & 7) == 0) {
        int h = lane >> 3;
        ((float*)(g_es4 + row0 + r0))[h] = es0;
        ((float*)(g_ed4 + row0 + r0))[h] = ed0;
        ((float*)(g_es4 + row0 + r1))[h] = es1;
        ((float*)(g_ed4 + row0 + r1))[h] = ed1;
    }
}

// ============ k_proj (layer 1): 16 rows/block, 4-deep W prefetch ============
__global__ void k_proj(const float* __restrict__ hin,
                       const float* __restrict__ W,
                       const float* __restrict__ as_,
                       const float* __restrict__ ad_)
{
    __shared__ __align__(16) float hr[16][DD];
    int row0 = blockIdx.x * 16, tid = threadIdx.x;
    {
        const float4* src = (const float4*)(hin + (size_t)row0*DD);
        float4* dst = (float4*)&hr[0][0];
        dst[tid] = src[tid];
        dst[tid + 256] = src[tid + 256];
    }
    __syncthreads();

    int w = tid >> 5, lane = tid & 31;
    int r0 = 2*w, r1 = 2*w + 1;
    float4 a0 = {0,0,0,0}, a1 = a0;
    {
        const float4* wp = (const float4*)W + lane;
        float4 p0 = wp[0], p1 = wp[32], p2 = wp[64], p3 = wp[96];
        for (int k = 0; k < DD-4; k += 4) {
            float4 n0 = wp[(k+4)*32], n1 = wp[(k+5)*32],
                   n2 = wp[(k+6)*32], n3 = wp[(k+7)*32];
            FMA2(p0, hr[r0][k  ], hr[r1][k  ], a0, a1);
            FMA2(p1, hr[r0][k+1], hr[r1][k+1], a0, a1);
            FMA2(p2, hr[r0][k+2], hr[r1][k+2], a0, a1);
            FMA2(p3, hr[r0][k+3], hr[r1][k+3], a0, a1);
            p0 = n0; p1 = n1; p2 = n2; p3 = n3;
        }
        FMA2(p0, hr[r0][124], hr[r1][124], a0, a1);
        FMA2(p1, hr[r0][125], hr[r1][125], a0, a1);
        FMA2(p2, hr[r0][126], hr[r1][126], a0, a1);
        FMA2(p3, hr[r0][127], hr[r1][127], a0, a1);
    }
    store_half8(g_xh + (size_t)(row0+r0)*DD + 4*lane, a0);
    store_half8(g_xh + (size_t)(row0+r1)*DD + 4*lane, a1);

    float4 av = *(const float4*)(as_ + 4*lane);
    float4 dv = *(const float4*)(ad_ + 4*lane);
    float es0 = a0.x*av.x + a0.y*av.y + a0.z*av.z + a0.w*av.w;
    float ed0 = a0.x*dv.x + a0.y*dv.y + a0.z*dv.z + a0.w*dv.w;
    float es1 = a1.x*av.x + a1.y*av.y + a1.z*av.z + a1.w*av.w;
    float ed1 = a1.x*dv.x + a1.y*dv.y + a1.z*dv.z + a1.w*dv.w;
    for (int o = 4; o; o >>= 1) {
        es0 += __shfl_xor_sync(0xffffffffu, es0, o);
        ed0 += __shfl_xor_sync(0xffffffffu, ed0, o);
        es1 += __shfl_xor_sync(0xffffffffu, es1, o);
        ed1 += __shfl_xor_sync(0xffffffffu, ed1, o);
    }
    if ((lane & 7) == 0) {
        int h = lane >> 3;
        ((float*)(g_es4 + row0 + r0))[h] = es0;
        ((float*)(g_ed4 + row0 + r0))[h] = ed0;
        ((float*)(g_es4 + row0 + r1))[h] = es1;
        ((float*)(g_ed4 + row0 + r1))[h] = ed1;
    }
}

// ============ k_gat: 4 rows/block, 2 warps/row (parity split), fp16 gather, __expf ============
// MODE 0: hout = hin + elu(agg + bias[128])
// MODE 1: g_hf = head-mean(agg) + bias[32]
template <int MODE>
__global__ void __launch_bounds__(256, 8) k_gat(
                      const float* __restrict__ hin,
                      const float* __restrict__ bias,
                      float* __restrict__ hout)
{
    int tid = threadIdx.x, w = tid >> 5, lane = tid & 31;
    int rsel = w >> 1, p = w & 1;
    int row0 = blockIdx.x * 4;
    int row = row0 + rsel;
    int bN = (row / NN) * NN;

    __shared__ int   soff_s[4][SDEG];
    __shared__ __align__(16) float salp_s[4][SDEG*4];
    __shared__ float ssum_s[4][2][HH];
    __shared__ float sinv_s[4][HH];
    __shared__ __align__(16) float spart_s[4][2][DD];

    int deg = g_deg[row];
    if (deg > SDEG) deg = SDEG;
    float4 edv = g_ed4[row];

    // phase 1: scores -> __expf, parity-split over k; per-head partial sums
    float4 sums = {0.f, 0.f, 0.f, 0.f};
    for (int k = p + 2*lane; k < deg; k += 64) {
        int j = g_adj[row*MAXDEG + k];
        soff_s[rsel][k] = (bN + j) * DD;
        float4 es = g_es4[bN + j];
        float4 s;
        s.x = edv.x + es.x; s.x = s.x >= 0.f ? s.x : 0.2f*s.x; s.x = __expf(s.x);
        s.y = edv.y + es.y; s.y = s.y >= 0.f ? s.y : 0.2f*s.y; s.y = __expf(s.y);
        s.z = edv.z + es.z; s.z = s.z >= 0.f ? s.z : 0.2f*s.z; s.z = __expf(s.z);
        s.w = edv.w + es.w; s.w = s.w >= 0.f ? s.w : 0.2f*s.w; s.w = __expf(s.w);
        sums.x += s.x; sums.y += s.y; sums.z += s.z; sums.w += s.w;
        *(float4*)(&salp_s[rsel][k*4]) = s;
    }
    for (int o = 16; o; o >>= 1) {
        sums.x += __shfl_xor_sync(0xffffffffu, sums.x, o);
        sums.y += __shfl_xor_sync(0xffffffffu, sums.y, o);
        sums.z += __shfl_xor_sync(0xffffffffu, sums.z, o);
        sums.w += __shfl_xor_sync(0xffffffffu, sums.w, o);
    }
    if (lane == 0) {
        ssum_s[rsel][p][0] = sums.x; ssum_s[rsel][p][1] = sums.y;
        ssum_s[rsel][p][2] = sums.z; ssum_s[rsel][p][3] = sums.w;
    }
    __syncthreads();
    if (p == 0 && lane < HH)
        sinv_s[rsel][lane] = 1.0f / (ssum_s[rsel][0][lane] + ssum_s[rsel][1][lane]);

    // phase 2: gather, parity-split, fp16 rows, MLP 4 per warp (8 per row)
    {
        const __half* base = g_xh + 4*lane;
        const int*   so = soff_s[rsel];
        const float* al = &salp_s[rsel][lane >> 3];
        float4 A0 = {0,0,0,0}, A1 = A0;
        int k = p;
        for (; k + 6 < deg; k += 8) {
            float a0 = al[4*k];       uint2 u0 = *(const uint2*)(base + so[k]);
            float a1 = al[4*(k+2)];   uint2 u1 = *(const uint2*)(base + so[k+2]);
            float a2 = al[4*(k+4)];   uint2 u2 = *(const uint2*)(base + so[k+4]);
            float a3 = al[4*(k+6)];   uint2 u3 = *(const uint2*)(base + so[k+6]);
            float2 f;
            f = __half22float2(*(__half2*)&u0.x); A0.x=fmaf(a0,f.x,A0.x); A0.y=fmaf(a0,f.y,A0.y);
            f = __half22float2(*(__half2*)&u0.y); A0.z=fmaf(a0,f.x,A0.z); A0.w=fmaf(a0,f.y,A0.w);
            f = __half22float2(*(__half2*)&u1.x); A1.x=fmaf(a1,f.x,A1.x); A1.y=fmaf(a1,f.y,A1.y);
            f = __half22float2(*(__half2*)&u1.y); A1.z=fmaf(a1,f.x,A1.z); A1.w=fmaf(a1,f.y,A1.w);
            f = __half22float2(*(__half2*)&u2.x); A0.x=fmaf(a2,f.x,A0.x); A0.y=fmaf(a2,f.y,A0.y);
            f = __half22float2(*(__half2*)&u2.y); A0.z=fmaf(a2,f.x,A0.z); A0.w=fmaf(a2,f.y,A0.w);
            f = __half22float2(*(__half2*)&u3.x); A1.x=fmaf(a3,f.x,A1.x); A1.y=fmaf(a3,f.y,A1.y);
            f = __half22float2(*(__half2*)&u3.y); A1.z=fmaf(a3,f.x,A1.z); A1.w=fmaf(a3,f.y,A1.w);
        }
        for (; k < deg; k += 2) {
            float a0 = al[4*k];       uint2 u0 = *(const uint2*)(base + so[k]);
            float2 f;
            f = __half22float2(*(__half2*)&u0.x); A0.x=fmaf(a0,f.x,A0.x); A0.y=fmaf(a0,f.y,A0.y);
            f = __half22float2(*(__half2*)&u0.y); A0.z=fmaf(a0,f.x,A0.z); A0.w=fmaf(a0,f.y,A0.w);
        }
        A0.x += A1.x; A0.y += A1.y; A0.z += A1.z; A0.w += A1.w;
        *(float4*)(&spart_s[rsel][p][4*lane]) = A0;
    }
    __syncthreads();

    // phase 3: combine parities, scale by softmax inverse, epilogue
    #pragma unroll
    for (int half = 0; half < 2; ++half) {
        int idx = tid + 256*half;            // 512 = 4 rows x 128 dims
        int r = idx >> 7, d = idx & 127;
        float v = (spart_s[r][0][d] + spart_s[r][1][d]) * sinv_s[r][d >> 5];
        if (MODE == 0) {
            float t = v + bias[d];
            float e = t > 0.f ? t : (__expf(t) - 1.f);      // ELU(alpha=1)
            hout[(size_t)(row0+r)*DD + d] = hin[(size_t)(row0+r)*DD + d] + e;
        } else {
            spart_s[r][0][d] = v;                           // staging for head-mean
        }
    }
    if (MODE == 1) {
        __syncthreads();
        if (tid < 4*CC) {
            int r = tid >> 5, c = tid & 31;
            g_hf[(size_t)(row0+r)*CC + c] =
                0.25f * (spart_s[r][0][c] + spart_s[r][0][32+c]
                       + spart_s[r][0][64+c] + spart_s[r][0][96+c]) + bias[c];
        }
    }
}

// ============ k_out: out = g_hf @ W_out + b_out ; 16 rows/block, Wout in smem ============
__global__ void k_out(const float* __restrict__ Wout,
                      const float* __restrict__ bout,
                      float* __restrict__ out)
{
    __shared__ __align__(16) float4 sW[CC*DD/4];   // 16 KB, loaded once per block
    __shared__ float shf[16*CC];                   // 2 KB
    int row0 = blockIdx.x * 16, tid = threadIdx.x;

    const float4* wsrc = (const float4*)Wout;
    #pragma unroll
    for (int i = 0; i < 4; ++i) sW[tid + 256*i] = wsrc[tid + 256*i];
    const float* hsrc = g_hf + (size_t)row0*CC;
    shf[tid] = hsrc[tid];
    shf[tid + 256] = hsrc[tid + 256];
    __syncthreads();

    #pragma unroll
    for (int it = 0; it < 2; ++it) {
        int idx = tid + 256*it;        // 512 items: (row r, float4-col q)
        int r = idx >> 5, q = idx & 31;
        float4 acc = *(const float4*)(bout + 4*q);
        const float* hr = shf + r*CC;
        #pragma unroll
        for (int c = 0; c < CC; ++c) {
            float x = hr[c];
            float4 wv = sW[c*32 + q];
            acc.x = fmaf(x, wv.x, acc.x); acc.y = fmaf(x, wv.y, acc.y);
            acc.z = fmaf(x, wv.z, acc.z); acc.w = fmaf(x, wv.w, acc.w);
        }
        *(float4*)(out + (size_t)(row0+r)*DD + 4*q) = acc;
    }
}

// ---------------- launch ----------------
extern "C" void kernel_launch(void* const* d_in, const int* in_sizes, int n_in,
                              void* d_out, int out_size)
{
    const float* x_alpha = (const float*)d_in[0];
    const float* sg      = (const float*)d_in[1];
    const float* W_in    = (const float*)d_in[2];
    const float* b_in    = (const float*)d_in[3];
    const float* ln_g    = (const float*)d_in[4];
    const float* ln_b    = (const float*)d_in[5];
    const float* W0      = (const float*)d_in[6];
    const float* as0     = (const float*)d_in[7];
    const float* ad0     = (const float*)d_in[8];
    const float* bias0   = (const float*)d_in[9];
    const float* W1      = (const float*)d_in[10];
    const float* as1     = (const float*)d_in[11];
    const float* ad1     = (const float*)d_in[12];
    const float* bias1   = (const float*)d_in[13];
    const float* W_out   = (const float*)d_in[14];
    const float* b_out   = (const float*)d_in[15];
    float* out = (float*)d_out;

    float *h, *h2;
    cudaGetSymbolAddress((void**)&h,  g_h);
    cudaGetSymbolAddress((void**)&h2, g_h2);

    k_front<<<FRONT_COMPUTE + ADJ_BLOCKS, 256>>>(x_alpha, W_in, b_in, ln_g, ln_b,
                                                 sg, W0, as0, ad0);
    k_gat<0><<<ROWS/4, 256>>>(h, bias0, h2);
    k_proj<<<ROWS/16, 256>>>(h2, W1, as1, ad1);
    k_gat<1><<<ROWS/4, 256>>>(nullptr, bias1, nullptr);
    k_out<<<ROWS/16, 256>>>(W_out, b_out, out);
}